// round 7
// baseline (speedup 1.0000x reference)
#include <cuda_runtime.h>
#include <cstdint>

#define NPIX 9216            // H*W = 96*96
#define BATCH 2
#define TOT (BATCH*NPIX)     // 18432
#define NBLK 444             // 148 SMs * 3 CTAs -- exactly one wave

__device__ float g_p[TOT];            // p = sigmoid(x0-x1)
__device__ float g_a[TOT];            // a = (2p-1)*log2(e)
__device__ unsigned int g_cnt[2];     // per-batch dynamic row queues

__device__ __forceinline__ float ex2(float x) {
    float r;
    asm("ex2.approx.ftz.f32 %0, %1;" : "=f"(r) : "f"(x));
    return r;
}

// Kernel 1: per-pixel prep + queue reset (runs once per replay)
__global__ void k_prep(const float* __restrict__ x) {
    int i = blockIdx.x * blockDim.x + threadIdx.x;
    if (i == 0) { g_cnt[0] = 0u; g_cnt[1] = 0u; }
    if (i >= TOT) return;
    int b = i / NPIX;
    int n = i - b * NPIX;
    float x0 = x[(size_t)(b * 2 + 0) * NPIX + n];
    float x1 = x[(size_t)(b * 2 + 1) * NPIX + n];
    float p = 1.0f / (1.0f + __expf(x1 - x0));
    g_p[i] = p;
    g_a[i] = (2.0f * p - 1.0f) * 1.4426950408889634f;  // log2(e)
}

// Kernel 2: persistent blocks; each binds to one batch, pulls rows from a
// global queue. p tile lives in smem for the whole block lifetime.
//   e_m = 2^(a_r * p_m) ; attn[row,m] = e_m / S ; y[row] fused conv1x1+sigmoid
__global__ void __launch_bounds__(256, 3)
k_attn(const float* __restrict__ w, const float* __restrict__ cb,
       const float* __restrict__ gm,
       float* __restrict__ y, float* __restrict__ attn) {
    const int tid = threadIdx.x;
    const int lane = tid & 31, wid = tid >> 5;
    const int b = blockIdx.x & 1;              // 222 blocks per batch

    __shared__ __align__(16) float sp[NPIX];   // 36 KB p tile (loaded once)
    __shared__ float sS[8], sT[8];
    __shared__ int sRow;

    {   // one-time tile load (L2-resident source, 36 KB)
        const float4* __restrict__ src = reinterpret_cast<const float4*>(g_p + b * NPIX);
        float4* dst = reinterpret_cast<float4*>(sp);
#pragma unroll
        for (int k = 0; k < 9; k++)
            dst[tid + k * 256] = src[tid + k * 256];
    }

    const float4* sp4 = reinterpret_cast<const float4*>(sp);

    for (;;) {
        if (tid == 0) sRow = (int)atomicAdd(&g_cnt[b], 1u);
        __syncthreads();                       // publish sRow; also fences sS/sT reuse
        const int n = sRow;
        if (n >= NPIX) break;
        const int row = b * NPIX + n;
        const float a2 = g_a[row];             // L2 hit

        float E[36];                   // full e cache: store phase = FMUL+STG only
        float S = 0.0f, T = 0.0f;
#pragma unroll
        for (int k = 0; k < 9; k++) {
            float4 pv = sp4[tid + k * 256];
            float e0 = ex2(a2 * pv.x);
            float e1 = ex2(a2 * pv.y);
            float e2 = ex2(a2 * pv.z);
            float e3 = ex2(a2 * pv.w);
            E[4*k+0]=e0; E[4*k+1]=e1; E[4*k+2]=e2; E[4*k+3]=e3;
            S += (e0 + e1) + (e2 + e3);
            T = fmaf(pv.x, e0, T); T = fmaf(pv.y, e1, T);
            T = fmaf(pv.z, e2, T); T = fmaf(pv.w, e3, T);
        }

        // block reduce S, T
#pragma unroll
        for (int o = 16; o > 0; o >>= 1) {
            S += __shfl_xor_sync(0xFFFFFFFFu, S, o);
            T += __shfl_xor_sync(0xFFFFFFFFu, T, o);
        }
        if (lane == 0) { sS[wid] = S; sT[wid] = T; }
        __syncthreads();
        float St = ((sS[0]+sS[1]) + (sS[2]+sS[3])) + ((sS[4]+sS[5]) + (sS[6]+sS[7]));
        float invS = 1.0f / St;

        if (tid == 0) {                // fused conv1x1 + sigmoid epilogue
            float Tt = ((sT[0]+sT[1]) + (sT[2]+sT[3])) + ((sT[4]+sT[5]) + (sT[6]+sT[7]));
            float o0 = Tt * invS;
            float p  = sp[n];
            float g  = gm[0];
            float pre0 = fmaf(g, o0, p);
            float pre1 = fmaf(g, 1.0f - o0, 1.0f - p);
            float t = fmaf(w[0], pre0, fmaf(w[1], pre1, cb[0]));
            y[row] = 1.0f / (1.0f + __expf(-t));
        }

        float4* __restrict__ out4 =
            reinterpret_cast<float4*>(attn + (size_t)row * NPIX);
#pragma unroll
        for (int k = 0; k < 9; k++) {
            float4 o;
            o.x = E[4*k+0] * invS;
            o.y = E[4*k+1] * invS;
            o.z = E[4*k+2] * invS;
            o.w = E[4*k+3] * invS;
            out4[tid + k * 256] = o;   // coalesced 128B streaming stores
        }
    }
}

extern "C" void kernel_launch(void* const* d_in, const int* in_sizes, int n_in,
                              void* d_out, int out_size) {
    const float* x  = (const float*)d_in[0];   // [2,2,96,96]
    const float* w  = (const float*)d_in[1];   // [2]
    const float* cb = (const float*)d_in[2];   // [1]
    const float* gm = (const float*)d_in[3];   // [1]
    float* out = (float*)d_out;                // [18432 y | 2*9216*9216 attn]

    k_prep<<<(TOT + 127) / 128, 128>>>(x);
    k_attn<<<NBLK, 256>>>(w, cb, gm, out, out + TOT);
}

// round 8
// speedup vs baseline: 1.1647x; 1.1647x over previous
#include <cuda_runtime.h>
#include <cstdint>

#define NPIX 9216            // H*W = 96*96
#define BATCH 2
#define TOT (BATCH*NPIX)     // 18432
#define RPB 6                // 3072 blocks = 6.92 waves of 444 -> nearly full last wave

__device__ float g_p[TOT];   // p = sigmoid(x0-x1)
__device__ float g_a[TOT];   // a = (2p-1)*log2(e)

__device__ __forceinline__ float ex2(float x) {
    float r;
    asm("ex2.approx.ftz.f32 %0, %1;" : "=f"(r) : "f"(x));
    return r;
}

// Kernel 1: per-pixel prep (float4-vectorized), signals dependent launch early.
__global__ void k_prep(const float* __restrict__ x) {
    int i = blockIdx.x * blockDim.x + threadIdx.x;   // quad index
    if (i < TOT / 4) {
        int b = (i * 4) / NPIX;
        int n4 = i - b * (NPIX / 4);
        const float4* x0 = reinterpret_cast<const float4*>(x + (size_t)(b * 2 + 0) * NPIX);
        const float4* x1 = reinterpret_cast<const float4*>(x + (size_t)(b * 2 + 1) * NPIX);
        float4 a = x0[n4], c = x1[n4];
        float4 p, q;
        p.x = 1.0f / (1.0f + __expf(c.x - a.x));
        p.y = 1.0f / (1.0f + __expf(c.y - a.y));
        p.z = 1.0f / (1.0f + __expf(c.z - a.z));
        p.w = 1.0f / (1.0f + __expf(c.w - a.w));
        const float L2E = 1.4426950408889634f;
        q.x = (2.0f * p.x - 1.0f) * L2E;
        q.y = (2.0f * p.y - 1.0f) * L2E;
        q.z = (2.0f * p.z - 1.0f) * L2E;
        q.w = (2.0f * p.w - 1.0f) * L2E;
        reinterpret_cast<float4*>(g_p)[i] = p;
        reinterpret_cast<float4*>(g_a)[i] = q;
    }
    asm volatile("griddepcontrol.launch_dependents;" ::: "memory");
}

// Kernel 2: RPB attention rows per block; p tile cached in smem.
//   e_m = 2^(a_r * p_m) ; attn[row,m] = e_m / S ; y[row] fused conv1x1+sigmoid
__global__ void __launch_bounds__(256, 3)
k_attn(const float* __restrict__ w, const float* __restrict__ cb,
       const float* __restrict__ gm,
       float* __restrict__ y, float* __restrict__ attn) {
    const int tid = threadIdx.x;
    const int lane = tid & 31, wid = tid >> 5;
    const int rowBase = blockIdx.x * RPB;      // 9216 % RPB == 0: no batch straddle
    const int b = rowBase / NPIX;

    __shared__ __align__(16) float sp[NPIX];   // 36 KB p tile
    __shared__ float sS[8], sT[8];

    asm volatile("griddepcontrol.wait;" ::: "memory");  // PDL: g_p/g_a ready

    {   // load p tile once per block (L2-resident source)
        const float4* __restrict__ src = reinterpret_cast<const float4*>(g_p + b * NPIX);
        float4* dst = reinterpret_cast<float4*>(sp);
#pragma unroll
        for (int k = 0; k < 9; k++)
            dst[tid + k * 256] = src[tid + k * 256];
    }
    __syncthreads();

    const float4* sp4 = reinterpret_cast<const float4*>(sp);

#pragma unroll 1
    for (int r = 0; r < RPB; r++) {
        const int row = rowBase + r;
        const float a2 = g_a[row];             // L2 hit

        float E[36];                   // full e cache: store phase = FMUL+STG only
        float S = 0.0f, T = 0.0f;
#pragma unroll
        for (int k = 0; k < 9; k++) {
            float4 pv = sp4[tid + k * 256];
            float e0 = ex2(a2 * pv.x);
            float e1 = ex2(a2 * pv.y);
            float e2 = ex2(a2 * pv.z);
            float e3 = ex2(a2 * pv.w);
            E[4*k+0]=e0; E[4*k+1]=e1; E[4*k+2]=e2; E[4*k+3]=e3;
            S += (e0 + e1) + (e2 + e3);
            T = fmaf(pv.x, e0, T); T = fmaf(pv.y, e1, T);
            T = fmaf(pv.z, e2, T); T = fmaf(pv.w, e3, T);
        }

        // block reduce S, T
#pragma unroll
        for (int o = 16; o > 0; o >>= 1) {
            S += __shfl_xor_sync(0xFFFFFFFFu, S, o);
            T += __shfl_xor_sync(0xFFFFFFFFu, T, o);
        }
        __syncthreads();               // protect sS/sT reuse across rows
        if (lane == 0) { sS[wid] = S; sT[wid] = T; }
        __syncthreads();
        float St = ((sS[0]+sS[1]) + (sS[2]+sS[3])) + ((sS[4]+sS[5]) + (sS[6]+sS[7]));
        float invS = 1.0f / St;

        if (tid == 0) {                // fused conv1x1 + sigmoid epilogue
            float Tt = ((sT[0]+sT[1]) + (sT[2]+sT[3])) + ((sT[4]+sT[5]) + (sT[6]+sT[7]));
            float o0 = Tt * invS;
            float p  = sp[row - b * NPIX];
            float g  = gm[0];
            float pre0 = fmaf(g, o0, p);
            float pre1 = fmaf(g, 1.0f - o0, 1.0f - p);
            float t = fmaf(w[0], pre0, fmaf(w[1], pre1, cb[0]));
            y[row] = 1.0f / (1.0f + __expf(-t));
        }

        float4* __restrict__ out4 =
            reinterpret_cast<float4*>(attn + (size_t)row * NPIX);
#pragma unroll
        for (int k = 0; k < 9; k++) {
            float4 o;
            o.x = E[4*k+0] * invS;
            o.y = E[4*k+1] * invS;
            o.z = E[4*k+2] * invS;
            o.w = E[4*k+3] * invS;
            out4[tid + k * 256] = o;   // coalesced 128B streaming stores
        }
    }
}

extern "C" void kernel_launch(void* const* d_in, const int* in_sizes, int n_in,
                              void* d_out, int out_size) {
    const float* x  = (const float*)d_in[0];   // [2,2,96,96]
    const float* w  = (const float*)d_in[1];   // [2]
    const float* cb = (const float*)d_in[2];   // [1]
    const float* gm = (const float*)d_in[3];   // [1]
    float* out = (float*)d_out;                // [18432 y | 2*9216*9216 attn]
    float* yp = out;
    float* attn = out + TOT;

    k_prep<<<(TOT / 4 + 255) / 256, 256>>>(x);

    // k_attn with Programmatic Dependent Launch: overlaps its launch ramp
    // with k_prep's execution; correctness via griddepcontrol.wait.
    cudaLaunchConfig_t cfg = {};
    cfg.gridDim  = dim3(TOT / RPB, 1, 1);
    cfg.blockDim = dim3(256, 1, 1);
    cfg.dynamicSmemBytes = 0;
    cfg.stream = 0;                    // legacy default stream (capture target)
    cudaLaunchAttribute attr[1];
    attr[0].id = cudaLaunchAttributeProgrammaticStreamSerialization;
    attr[0].val.programmaticStreamSerializationAllowed = 1;
    cfg.attrs = attr;
    cfg.numAttrs = 1;
    cudaLaunchKernelEx(&cfg, k_attn, w, cb, gm, yp, attn);
}